// round 1
// baseline (speedup 1.0000x reference)
#include <cuda_runtime.h>
#include <math.h>

#define BB 16
#define HH 512
#define WW 512
#define HW (HH*WW)
#define NPIX (BB*HW)

// ---------------- scratch (device globals: alloc-free rule) ----------------
static __device__ float         g_gray[NPIX];
static __device__ int           g_hist[BB*32];
static __device__ float         g_thr[BB];
static __device__ unsigned char g_bufA[NPIX];
static __device__ unsigned char g_bufB[NPIX];
static __device__ unsigned char g_nuc[NPIX];
static __device__ unsigned char g_cell[NPIX];
static __device__ unsigned char g_bnd[NPIX];
static __device__ float         g_sn[NPIX];
static __device__ float         g_cs[NPIX];
static __device__ float         g_v0[NPIX], g_v1[NPIX], g_v2[NPIX], g_v3[NPIX], g_v4[NPIX], g_v5[NPIX];
static __device__ float         g_par[13];   // sp(cal_a)[4], cal_b[4], alpha[4], tau
static __device__ float         g_red[BB*2]; // per-batch max, sumexp

#define COORDS \
    int x = blockIdx.x*blockDim.x + threadIdx.x; \
    int y = blockIdx.y*blockDim.y + threadIdx.y; \
    int b = blockIdx.z; \
    size_t i = (size_t)b*HW + (size_t)y*WW + x;

__device__ __forceinline__ float softplusf(float v){
    return fmaxf(v, 0.0f) + log1pf(expf(-fabsf(v)));
}

// ---------------- gray + histogram ----------------
__global__ void k_zero_hist(){
    int i = blockIdx.x*blockDim.x + threadIdx.x;
    if (i < BB*32) g_hist[i] = 0;
}

__global__ void k_gray_hist(const float* __restrict__ img){
    __shared__ int sh[32];
    int t = threadIdx.x;
    if (t < 32) sh[t] = 0;
    __syncthreads();
    int b = blockIdx.y;
    int p = blockIdx.x*blockDim.x + t;
    const float* im = img + (size_t)b*3*HW;
    float r  = im[p];
    float gg = im[HW + p];
    float bl = im[2*HW + p];
    float gray = 0.5f*(0.299f*r + 0.587f*gg + 0.114f*bl + 1.0f);
    gray = fminf(fmaxf(gray, 0.0f), 1.0f);
    g_gray[(size_t)b*HW + p] = gray;
    int idx = (int)(gray*32.0f);
    idx = idx < 0 ? 0 : (idx > 31 ? 31 : idx);
    atomicAdd(&sh[idx], 1);
    __syncthreads();
    if (t < 32) atomicAdd(&g_hist[b*32 + t], sh[t]);
}

// ---------------- Otsu (exact float32 replication) ----------------
__global__ void k_otsu(){
    int b = blockIdx.x;
    if (threadIdx.x != 0) return;
    float omega[32], mu[32];
    float denom = (float)HW + 1e-6f;
    float o = 0.0f, m = 0.0f;
    for (int k = 0; k < 32; k++){
        float pk = (float)g_hist[b*32 + k] / denom;
        float xk = (float)k / 31.0f;
        o += pk;
        m += pk*xk;
        omega[k] = o; mu[k] = m;
    }
    float mu_t = mu[31];
    float best = -1e30f; int kb = 0;
    for (int k = 0; k < 32; k++){
        float num = mu_t*omega[k] - mu[k];
        float s   = num*num / (omega[k]*(1.0f - omega[k]) + 1e-8f);
        if (s > best){ best = s; kb = k; }   // first-max, like jnp.argmax
    }
    g_thr[b] = (float)kb / 32.0f;            // edges[kbest]
}

// ---------------- scalar params ----------------
__global__ void k_params(const float* __restrict__ cal_a, const float* __restrict__ cal_b,
                         const float* __restrict__ alpha_logits, const float* __restrict__ tau_p){
    if (threadIdx.x == 0 && blockIdx.x == 0){
        float al[4]; float mx = -1e30f;
        for (int c = 0; c < 4; c++){ al[c] = alpha_logits[c]; mx = fmaxf(mx, al[c]); }
        float s = 0.0f;
        for (int c = 0; c < 4; c++){ al[c] = expf(al[c] - mx); s += al[c]; }
        for (int c = 0; c < 4; c++){
            g_par[c]     = softplusf(cal_a[c]);
            g_par[4 + c] = cal_b[c];
            g_par[8 + c] = al[c]/s;
        }
        g_par[12] = 0.2f + softplusf(tau_p[0]);
    }
}

// ---------------- morphology ----------------
__device__ __forceinline__ unsigned char pool3(const unsigned char* __restrict__ p, int y, int x, bool maxp){
    int y0 = y-1 < 0 ? 0 : y-1, y1 = y+1 > HH-1 ? HH-1 : y+1;
    int x0 = x-1 < 0 ? 0 : x-1, x1 = x+1 > WW-1 ? WW-1 : x+1;
    unsigned char v = maxp ? 0 : 1;
    for (int yy = y0; yy <= y1; yy++)
        for (int xx = x0; xx <= x1; xx++){
            unsigned char u = p[yy*WW + xx];
            v = maxp ? (unsigned char)(v | u) : (unsigned char)(v & u);
        }
    return v;
}

__global__ void k_nuc0_erode(){    // nuc0 = gray<=thr computed on the fly; erode3 -> bufA
    COORDS;
    float thr = g_thr[b];
    const float* g = g_gray + (size_t)b*HW;
    int y0 = y-1 < 0 ? 0 : y-1, y1 = y+1 > HH-1 ? HH-1 : y+1;
    int x0 = x-1 < 0 ? 0 : x-1, x1 = x+1 > WW-1 ? WW-1 : x+1;
    unsigned char v = 1;
    for (int yy = y0; yy <= y1; yy++)
        for (int xx = x0; xx <= x1; xx++)
            v &= (unsigned char)(g[yy*WW + xx] <= thr);
    g_bufA[i] = v;
}

__global__ void k_dil_A2B(){ COORDS; g_bufB[i] = pool3(g_bufA + (size_t)b*HW, y, x, true ); }
__global__ void k_dil_B2A(){ COORDS; g_bufA[i] = pool3(g_bufB + (size_t)b*HW, y, x, true ); }
__global__ void k_ero_A2nuc(){ COORDS; g_nuc[i] = pool3(g_bufA + (size_t)b*HW, y, x, false); }

// boundary = nuc - erode(nuc); also emit nuc (float) output
__global__ void k_bnd(float* __restrict__ out){
    COORDS;
    unsigned char n  = g_nuc[i];
    unsigned char er = pool3(g_nuc + (size_t)b*HW, y, x, false);
    g_bnd[i] = (unsigned char)(n & (unsigned char)(1 - er));
    out[5*(size_t)NPIX + i] = (float)n;          // nuc output
}

// cell = maxpool(nuc,11), separable
__global__ void k_rowmax11(){
    COORDS;
    const unsigned char* p = g_nuc + (size_t)b*HW + (size_t)y*WW;
    int x0 = x-5 < 0 ? 0 : x-5, x1 = x+5 > WW-1 ? WW-1 : x+5;
    unsigned char v = 0;
    for (int xx = x0; xx <= x1; xx++) v |= p[xx];
    g_bufA[i] = v;
}
__global__ void k_colmax11(){
    COORDS;
    const unsigned char* p = g_bufA + (size_t)b*HW;
    int y0 = y-5 < 0 ? 0 : y-5, y1 = y+5 > HH-1 ? HH-1 : y+5;
    unsigned char v = 0;
    for (int yy = y0; yy <= y1; yy++) v |= p[yy*WW + x];
    g_cell[i] = v;
}

// ---------------- sobel -> unit orientation vector ----------------
__global__ void k_sobel(){
    COORDS;
    const float* g = g_gray + (size_t)b*HW;
    float v00 = (y>0    && x>0   ) ? g[(y-1)*WW + x-1] : 0.0f;
    float v01 = (y>0             ) ? g[(y-1)*WW + x  ] : 0.0f;
    float v02 = (y>0    && x<WW-1) ? g[(y-1)*WW + x+1] : 0.0f;
    float v10 = (x>0             ) ? g[ y   *WW + x-1] : 0.0f;
    float v12 = (x<WW-1          ) ? g[ y   *WW + x+1] : 0.0f;
    float v20 = (y<HH-1 && x>0   ) ? g[(y+1)*WW + x-1] : 0.0f;
    float v21 = (y<HH-1          ) ? g[(y+1)*WW + x  ] : 0.0f;
    float v22 = (y<HH-1 && x<WW-1) ? g[(y+1)*WW + x+1] : 0.0f;
    float gx = (v00 + 2.0f*v10 + v20) - (v02 + 2.0f*v12 + v22);
    float gy = (v00 + 2.0f*v01 + v02) - (v20 + 2.0f*v21 + v22);
    float r = sqrtf(gx*gx + gy*gy);
    float sn, cs;
    if (r > 0.0f){ sn = gy/r; cs = gx/r; } else { sn = 0.0f; cs = 1.0f; }
    g_sn[i] = sn; g_cs[i] = cs;
}

// ---------------- vertical 9-sums of [sin, cos, gray, gray^2, nuc, cell] ----------------
__global__ void k_vsum(){
    COORDS;
    int y0 = y-4 < 0 ? 0 : y-4, y1 = y+4 > HH-1 ? HH-1 : y+4;
    float s0=0,s1=0,s2=0,s3=0,s4=0,s5=0;
    size_t base = (size_t)b*HW + x;
    for (int yy = y0; yy <= y1; yy++){
        size_t j = base + (size_t)yy*WW;
        s0 += g_sn[j];
        s1 += g_cs[j];
        float gv = g_gray[j];
        s2 += gv;
        s3 += gv*gv;
        s4 += (float)g_nuc[j];
        s5 += (float)g_cell[j];
    }
    g_v0[i]=s0; g_v1[i]=s1; g_v2[i]=s2; g_v3[i]=s3; g_v4[i]=s4; g_v5[i]=s5;
}

// ---------------- horizontal 9-sums + z1,z2,z3 ----------------
__global__ void k_hsum_final(float* __restrict__ out){
    COORDS;
    int x0 = x-4 < 0 ? 0 : x-4, x1 = x+4 > WW-1 ? WW-1 : x+4;
    float s0=0,s1=0,s2=0,s3=0,s4=0,s5=0;
    size_t row = (size_t)b*HW + (size_t)y*WW;
    for (int xx = x0; xx <= x1; xx++){
        size_t j = row + xx;
        s0 += g_v0[j]; s1 += g_v1[j]; s2 += g_v2[j];
        s3 += g_v3[j]; s4 += g_v4[j]; s5 += g_v5[j];
    }
    int yy0 = y-4 < 0 ? 0 : y-4, yy1 = y+4 > HH-1 ? HH-1 : y+4;
    float cnt = (float)((yy1-yy0+1)*(x1-x0+1));
    float den = cnt + 1e-6f;
    float ms = s0/den, mc = s1/den;
    float circ = 1.0f - sqrtf(ms*ms + mc*mc + 1e-6f);
    float An = s4;
    float Ac = fmaxf(s5 - s4, 1.0f);
    float ncv = An/Ac;
    float g1 = s2/den, g2 = s3/den;
    float ent = log1pf(fmaxf(g2 - g1*g1, 0.0f));
    float* z = out + (size_t)NPIX + (size_t)b*4*HW + (size_t)y*WW + x;
    z[HW]   = circ;  // z_maps[1]
    z[2*HW] = ncv;   // z_maps[2]
    z[3*HW] = ent;   // z_maps[3]
}

// ---------------- roughness (z_maps[0]) ----------------
__global__ void k_rough(float* __restrict__ out){
    COORDS;
    const unsigned char* n = g_nuc + (size_t)b*HW;
    float c  = (float)n[y*WW + x];
    float up = (y > 0   ) ? (float)n[(y-1)*WW + x] : 0.0f;
    float dn = (y < HH-1) ? (float)n[(y+1)*WW + x] : 0.0f;
    float lf = (x > 0   ) ? (float)n[y*WW + x-1]   : 0.0f;
    float rt = (x < WW-1) ? (float)n[y*WW + x+1]   : 0.0f;
    float lap = fabsf(up + dn + lf + rt - 4.0f*c);
    const unsigned char* bd = g_bnd + (size_t)b*HW;
    float bc = (float)bd[y*WW + x];
    int y0 = y-2 < 0 ? 0 : y-2, y1 = y+2 > HH-1 ? HH-1 : y+2;
    int x0 = x-2 < 0 ? 0 : x-2, x1 = x+2 > WW-1 ? WW-1 : x+2;
    float s = 0.0f;
    for (int yy = y0; yy <= y1; yy++)
        for (int xx = x0; xx <= x1; xx++)
            s += (float)bd[yy*WW + xx];
    float rough = lap*bc / (s + 1e-6f);
    out[(size_t)NPIX + (size_t)b*4*HW + (size_t)y*WW + x] = rough;
}

// ---------------- energy E_t ----------------
__global__ void k_energy(float* __restrict__ out){
    int b = blockIdx.y;
    int p = blockIdx.x*blockDim.x + threadIdx.x;
    const float* z = out + (size_t)NPIX + (size_t)b*4*HW + p;
    float z0 = log1pf(fmaxf(z[0], 0.0f));
    float z1 = fminf(fmaxf(z[HW], 0.0f), 1.0f);
    float z2 = log1pf(fmaxf(z[2*HW], 0.0f));
    float z3 = fminf(fmaxf(z[3*HW], 0.0f), 3.4657359f);
    float E = g_par[8 ]*(g_par[0]*z0 + g_par[4])
            + g_par[9 ]*(g_par[1]*z1 + g_par[5])
            + g_par[10]*(g_par[2]*z2 + g_par[6])
            + g_par[11]*(g_par[3]*z3 + g_par[7]);
    out[6*(size_t)NPIX + (size_t)b*HW + p] = E;
}

// ---------------- softmax reduce ----------------
__global__ void k_reduce(const float* __restrict__ out){
    __shared__ float sm[512];
    int b = blockIdx.x;
    const float* E = out + 6*(size_t)NPIX + (size_t)b*HW;
    float invtau = 1.0f / g_par[12];
    float m = -1e30f;
    for (int p = threadIdx.x; p < HW; p += blockDim.x)
        m = fmaxf(m, -E[p]*invtau);
    sm[threadIdx.x] = m; __syncthreads();
    for (int s = blockDim.x/2; s > 0; s >>= 1){
        if (threadIdx.x < s) sm[threadIdx.x] = fmaxf(sm[threadIdx.x], sm[threadIdx.x + s]);
        __syncthreads();
    }
    m = sm[0]; __syncthreads();
    float acc = 0.0f;
    for (int p = threadIdx.x; p < HW; p += blockDim.x)
        acc += expf(-E[p]*invtau - m);
    sm[threadIdx.x] = acc; __syncthreads();
    for (int s = blockDim.x/2; s > 0; s >>= 1){
        if (threadIdx.x < s) sm[threadIdx.x] += sm[threadIdx.x + s];
        __syncthreads();
    }
    if (threadIdx.x == 0){ g_red[b*2] = m; g_red[b*2+1] = sm[0]; }
}

__global__ void k_A(float* __restrict__ out){
    int b = blockIdx.y;
    int p = blockIdx.x*blockDim.x + threadIdx.x;
    float invtau = 1.0f / g_par[12];
    float m = g_red[b*2];
    float s = g_red[b*2+1];
    float E = out[6*(size_t)NPIX + (size_t)b*HW + p];
    out[(size_t)b*HW + p] = expf(-E*invtau - m) / s;
}

// ---------------- launch ----------------
extern "C" void kernel_launch(void* const* d_in, const int* in_sizes, int n_in,
                              void* d_out, int out_size){
    const float* img    = (const float*)d_in[0];
    const float* cal_a  = (const float*)d_in[1];
    const float* cal_b  = (const float*)d_in[2];
    const float* alpha  = (const float*)d_in[3];
    const float* tau_p  = (const float*)d_in[4];
    float* out = (float*)d_out;
    (void)in_sizes; (void)n_in; (void)out_size;

    dim3 blk(32, 8, 1);
    dim3 grd(WW/32, HH/8, BB);
    dim3 blk1(256, 1, 1);
    dim3 grd1(HW/256, BB, 1);

    k_zero_hist<<<2, 256>>>();
    k_gray_hist<<<grd1, blk1>>>(img);
    k_otsu<<<BB, 32>>>();
    k_params<<<1, 32>>>(cal_a, cal_b, alpha, tau_p);

    k_nuc0_erode<<<grd, blk>>>();
    k_dil_A2B<<<grd, blk>>>();
    k_dil_B2A<<<grd, blk>>>();
    k_ero_A2nuc<<<grd, blk>>>();

    k_bnd<<<grd, blk>>>(out);
    k_rowmax11<<<grd, blk>>>();
    k_colmax11<<<grd, blk>>>();

    k_sobel<<<grd, blk>>>();
    k_vsum<<<grd, blk>>>();
    k_hsum_final<<<grd, blk>>>(out);
    k_rough<<<grd, blk>>>(out);

    k_energy<<<grd1, blk1>>>(out);
    k_reduce<<<BB, 512>>>(out);
    k_A<<<grd1, blk1>>>(out);
}

// round 2
// speedup vs baseline: 1.5029x; 1.5029x over previous
#include <cuda_runtime.h>
#include <math.h>

#define BB 16
#define HH 512
#define WW 512
#define HW (HH*WW)
#define NPIX (BB*HW)
#define WORDS_ROW 16           // 512/32
#define WORDS_IMG (HH*WORDS_ROW)

// ---------------- scratch (device globals: alloc-free rule) ----------------
static __device__ float    g_gray[NPIX];
static __device__ int      g_hist[BB*32];
static __device__ float    g_thr[BB];
static __device__ unsigned g_nucbits[BB*WORDS_IMG];
static __device__ unsigned g_cellbits[BB*WORDS_IMG];
static __device__ unsigned g_bndbits[BB*WORDS_IMG];
static __device__ float    g_par[13];          // sp(cal_a)[4], cal_b[4], alpha[4], tau
static __device__ float    g_part[BB*256*2];   // per-tile (max, sumexp)
static __device__ float    g_red[BB*2];        // per-batch (max, sumexp)

__device__ __forceinline__ float softplusf(float v){
    return fmaxf(v, 0.0f) + log1pf(expf(-fabsf(v)));
}

// ---------------- gray + histogram ----------------
__global__ void k_zero_hist(){
    int i = blockIdx.x*blockDim.x + threadIdx.x;
    if (i < BB*32) g_hist[i] = 0;
}

__global__ void k_gray_hist(const float* __restrict__ img){
    __shared__ int sh[32];
    int t = threadIdx.x;
    if (t < 32) sh[t] = 0;
    __syncthreads();
    int b = blockIdx.y;
    int p = blockIdx.x*blockDim.x + t;
    const float* im = img + (size_t)b*3*HW;
    float r  = im[p];
    float gg = im[HW + p];
    float bl = im[2*HW + p];
    float gray = 0.5f*(0.299f*r + 0.587f*gg + 0.114f*bl + 1.0f);
    gray = fminf(fmaxf(gray, 0.0f), 1.0f);
    g_gray[(size_t)b*HW + p] = gray;
    int idx = (int)(gray*32.0f);
    idx = idx < 0 ? 0 : (idx > 31 ? 31 : idx);
    atomicAdd(&sh[idx], 1);
    __syncthreads();
    if (t < 32) atomicAdd(&g_hist[b*32 + t], sh[t]);
}

// ---------------- Otsu + scalar params ----------------
__global__ void k_otsu_params(const float* __restrict__ cal_a, const float* __restrict__ cal_b,
                              const float* __restrict__ alpha_logits, const float* __restrict__ tau_p){
    int b = blockIdx.x;
    if (threadIdx.x != 0) return;
    float omega[32], mu[32];
    float denom = (float)HW + 1e-6f;
    float o = 0.0f, m = 0.0f;
    for (int k = 0; k < 32; k++){
        float pk = (float)g_hist[b*32 + k] / denom;
        float xk = (float)k / 31.0f;
        o += pk; m += pk*xk;
        omega[k] = o; mu[k] = m;
    }
    float mu_t = mu[31];
    float best = -1e30f; int kb = 0;
    for (int k = 0; k < 32; k++){
        float num = mu_t*omega[k] - mu[k];
        float s   = num*num / (omega[k]*(1.0f - omega[k]) + 1e-8f);
        if (s > best){ best = s; kb = k; }
    }
    g_thr[b] = (float)kb / 32.0f;
    if (b == 0){
        float al[4]; float mx = -1e30f;
        for (int c = 0; c < 4; c++){ al[c] = alpha_logits[c]; mx = fmaxf(mx, al[c]); }
        float s = 0.0f;
        for (int c = 0; c < 4; c++){ al[c] = expf(al[c] - mx); s += al[c]; }
        for (int c = 0; c < 4; c++){
            g_par[c]     = softplusf(cal_a[c]);
            g_par[4 + c] = cal_b[c];
            g_par[8 + c] = al[c]/s;
        }
        g_par[12] = 0.2f + softplusf(tau_p[0]);
    }
}

// ---------------- bit-packed morphology: one block per image ----------------
__device__ __forceinline__ unsigned h_ero(const unsigned* S, int y, int k){
    unsigned w = S[y*WORDS_ROW + k];
    unsigned p = (k > 0)             ? S[y*WORDS_ROW + k - 1] : 0u;
    unsigned n = (k < WORDS_ROW - 1) ? S[y*WORDS_ROW + k + 1] : 0u;
    unsigned L = (w << 1) | ((k > 0)             ? (p >> 31) : 1u);
    unsigned R = (w >> 1) | ((k < WORDS_ROW - 1) ? (n << 31) : 0x80000000u);
    return L & w & R;
}
__device__ __forceinline__ unsigned h_dil(const unsigned* S, int y, int k){
    unsigned w = S[y*WORDS_ROW + k];
    unsigned p = (k > 0)             ? S[y*WORDS_ROW + k - 1] : 0u;
    unsigned n = (k < WORDS_ROW - 1) ? S[y*WORDS_ROW + k + 1] : 0u;
    unsigned L = (w << 1) | (p >> 31);
    unsigned R = (w >> 1) | (n << 31);
    return L | w | R;
}
__device__ __forceinline__ unsigned erode3w(const unsigned* S, int y, int k){
    unsigned v = h_ero(S, y, k);
    if (y > 0)      v &= h_ero(S, y-1, k);
    if (y < HH - 1) v &= h_ero(S, y+1, k);
    return v;
}
__device__ __forceinline__ unsigned dilate3w(const unsigned* S, int y, int k){
    unsigned v = h_dil(S, y, k);
    if (y > 0)      v |= h_dil(S, y-1, k);
    if (y < HH - 1) v |= h_dil(S, y+1, k);
    return v;
}

__global__ void __launch_bounds__(1024) k_morph(){
    __shared__ unsigned S[WORDS_IMG];   // 32 KB: whole binary image
    int b   = blockIdx.x;
    int tid = threadIdx.x;
    float thr = g_thr[b];
    const float* g = g_gray + (size_t)b*HW;

    // threshold -> bits
    #pragma unroll
    for (int s = 0; s < 8; s++){
        int idx = tid + s*1024;
        int y = idx >> 4, k = idx & 15;
        const float* row = g + y*WW + k*32;
        unsigned w = 0;
        #pragma unroll
        for (int j = 0; j < 32; j++)
            w |= (row[j] <= thr) ? (1u << j) : 0u;
        S[idx] = w;
    }
    __syncthreads();

    unsigned nv[8];
    // min3
    #pragma unroll
    for (int s = 0; s < 8; s++){ int idx = tid + s*1024; nv[s] = erode3w(S, idx >> 4, idx & 15); }
    __syncthreads();
    #pragma unroll
    for (int s = 0; s < 8; s++) S[tid + s*1024] = nv[s];
    __syncthreads();
    // max3
    #pragma unroll
    for (int s = 0; s < 8; s++){ int idx = tid + s*1024; nv[s] = dilate3w(S, idx >> 4, idx & 15); }
    __syncthreads();
    #pragma unroll
    for (int s = 0; s < 8; s++) S[tid + s*1024] = nv[s];
    __syncthreads();
    // max3
    #pragma unroll
    for (int s = 0; s < 8; s++){ int idx = tid + s*1024; nv[s] = dilate3w(S, idx >> 4, idx & 15); }
    __syncthreads();
    #pragma unroll
    for (int s = 0; s < 8; s++) S[tid + s*1024] = nv[s];
    __syncthreads();
    // min3 -> nuc
    #pragma unroll
    for (int s = 0; s < 8; s++){ int idx = tid + s*1024; nv[s] = erode3w(S, idx >> 4, idx & 15); }
    __syncthreads();
    #pragma unroll
    for (int s = 0; s < 8; s++) S[tid + s*1024] = nv[s];
    __syncthreads();

    // nuc bits out; bnd = nuc & ~erode3(nuc)
    #pragma unroll
    for (int s = 0; s < 8; s++){
        int idx = tid + s*1024;
        unsigned nu = S[idx];
        unsigned er = erode3w(S, idx >> 4, idx & 15);
        g_nucbits[b*WORDS_IMG + idx] = nu;
        g_bndbits[b*WORDS_IMG + idx] = nu & ~er;
    }
    // rowmax11 (reads S=nuc)
    #pragma unroll
    for (int s = 0; s < 8; s++){
        int idx = tid + s*1024;
        int y = idx >> 4, k = idx & 15;
        unsigned w = S[y*WORDS_ROW + k];
        unsigned p = (k > 0)             ? S[y*WORDS_ROW + k - 1] : 0u;
        unsigned n = (k < WORDS_ROW - 1) ? S[y*WORDS_ROW + k + 1] : 0u;
        unsigned long long lo = ((unsigned long long)w << 32) | p;
        unsigned long long hi = ((unsigned long long)n << 32) | w;
        unsigned v = w;
        #pragma unroll
        for (int sh = 1; sh <= 5; sh++){
            v |= (unsigned)(lo >> (32 - sh));
            v |= (unsigned)(hi >> sh);
        }
        nv[s] = v;
    }
    __syncthreads();
    #pragma unroll
    for (int s = 0; s < 8; s++) S[tid + s*1024] = nv[s];
    __syncthreads();
    // colmax11 -> cell bits out
    #pragma unroll
    for (int s = 0; s < 8; s++){
        int idx = tid + s*1024;
        int y = idx >> 4, k = idx & 15;
        int y0 = y-5 < 0 ? 0 : y-5, y1 = y+5 > HH-1 ? HH-1 : y+5;
        unsigned v = 0;
        for (int yy = y0; yy <= y1; yy++) v |= S[yy*WORDS_ROW + k];
        g_cellbits[b*WORDS_IMG + idx] = v;
    }
}

// ---------------- fused maps kernel ----------------
__device__ __forceinline__ unsigned winN(const unsigned* w3, int rel, int width){
    // rel in [0,61], width <= 9, window may spill into w3[2]
    unsigned long long c = ((unsigned long long)w3[1] << 32) | (unsigned long long)w3[0];
    unsigned long long v = c >> rel;
    if (rel + width > 64) v |= ((unsigned long long)w3[2]) << (64 - rel);
    return (unsigned)v & ((1u << width) - 1u);
}
__device__ __forceinline__ unsigned bit1(const unsigned* w3, int pos){   // pos in [0,95]
    return (w3[pos >> 5] >> (pos & 31)) & 1u;
}

__global__ void __launch_bounds__(1024) k_fused(float* __restrict__ out){
    __shared__ float sg[42*43];
    __shared__ float ssn[40*40];
    __shared__ float scs[40*40];
    __shared__ float vs0[32*40], vs1[32*40], vs2[32*40], vs3[32*40];
    __shared__ unsigned nucw[40*3], cellw[40*3], bndw[40*3];

    int tx = threadIdx.x, ty = threadIdx.y;
    int tid = ty*32 + tx;
    int tx0 = blockIdx.x*32, ty0 = blockIdx.y*32;
    int b = blockIdx.z;
    const float* g = g_gray + (size_t)b*HW;

    // load gray tile with halo 5, zeros outside image
    for (int idx = tid; idx < 42*42; idx += 1024){
        int rr = idx/42, cc = idx%42;
        int gy = ty0 - 5 + rr, gx = tx0 - 5 + cc;
        float v = 0.0f;
        if (gy >= 0 && gy < HH && gx >= 0 && gx < WW) v = g[gy*WW + gx];
        sg[rr*43 + cc] = v;
    }
    // load bit rows (40 rows x 3 words), zeros outside
    {
        int kw0 = (tx0 >> 5) - 1;
        for (int idx = tid; idx < 120; idx += 1024){
            int r = idx/3, c = idx%3;
            int gy = ty0 - 4 + r;
            int kw = kw0 + c;
            unsigned nv = 0, cv = 0, bv = 0;
            if (gy >= 0 && gy < HH && kw >= 0 && kw < WORDS_ROW){
                int off = b*WORDS_IMG + gy*WORDS_ROW + kw;
                nv = g_nucbits[off]; cv = g_cellbits[off]; bv = g_bndbits[off];
            }
            nucw[idx] = nv; cellw[idx] = cv; bndw[idx] = bv;
        }
    }
    __syncthreads();

    // stage1: sobel -> sin/cos at 40x40 (zero outside image)
    for (int idx = tid; idx < 40*40; idx += 1024){
        int r = idx/40, c = idx%40;
        int gy = ty0 - 4 + r, gx = tx0 - 4 + c;
        float sn = 0.0f, cs = 0.0f;
        if (gy >= 0 && gy < HH && gx >= 0 && gx < WW){
            const float* p = sg + r*43 + c;   // p[0] = image(gy-1, gx-1)
            float v00 = p[0],     v01 = p[1],      v02 = p[2];
            float v10 = p[43],                      v12 = p[45];
            float v20 = p[86],    v21 = p[87],     v22 = p[88];
            float gxv = (v00 + 2.0f*v10 + v20) - (v02 + 2.0f*v12 + v22);
            float gyv = (v00 + 2.0f*v01 + v02) - (v20 + 2.0f*v21 + v22);
            float r2 = gxv*gxv + gyv*gyv;
            if (r2 > 0.0f){
                float rr = sqrtf(r2);
                sn = gyv/rr; cs = gxv/rr;
            } else { sn = 0.0f; cs = 1.0f; }
        }
        ssn[idx] = sn; scs[idx] = cs;
    }
    __syncthreads();

    // stage2: vertical 9-sums (32 out-rows x 40 cols)
    for (int idx = tid; idx < 32*40; idx += 1024){
        int yi = idx/40, j = idx%40;
        float a = 0.0f, bq = 0.0f, cq = 0.0f, dq = 0.0f;
        #pragma unroll
        for (int k = 0; k < 9; k++){
            a  += ssn[(yi+k)*40 + j];
            bq += scs[(yi+k)*40 + j];
            float gv = sg[(yi+1+k)*43 + (j+1)];
            cq += gv;
            dq += gv*gv;
        }
        vs0[idx] = a; vs1[idx] = bq; vs2[idx] = cq; vs3[idx] = dq;
    }
    __syncthreads();

    // stage3: horizontal 9-sums + bit stats + final maps + energy
    int xi = tx, yi = ty;
    int gx = tx0 + xi, gy = ty0 + yi;
    float s_sn = 0.0f, s_cs = 0.0f, s_g = 0.0f, s_g2 = 0.0f;
    #pragma unroll
    for (int k = 0; k < 9; k++){
        int j = yi*40 + xi + k;
        s_sn += vs0[j]; s_cs += vs1[j]; s_g += vs2[j]; s_g2 += vs3[j];
    }
    int rows_in = (gy+4 > HH-1 ? HH-1 : gy+4) - (gy-4 < 0 ? 0 : gy-4) + 1;
    int cols_in = (gx+4 > WW-1 ? WW-1 : gx+4) - (gx-4 < 0 ? 0 : gx-4) + 1;
    float den = (float)(rows_in*cols_in) + 1e-6f;

    float ms = s_sn/den, mc = s_cs/den;
    float circ = 1.0f - sqrtf(ms*ms + mc*mc + 1e-6f);
    float g1 = s_g/den, g2v = s_g2/den;
    float ent = log1pf(fmaxf(g2v - g1*g1, 0.0f));

    int an = 0, csum = 0;
    #pragma unroll
    for (int k = 0; k < 9; k++){
        an   += __popc(winN(&nucw[(yi+k)*3],  xi + 28, 9));
        csum += __popc(winN(&cellw[(yi+k)*3], xi + 28, 9));
    }
    float A_n = (float)an;
    float A_c = fmaxf((float)(csum - an), 1.0f);
    float ncv = A_n / A_c;

    unsigned cbit = bit1(&nucw[(yi+4)*3], xi + 32);
    unsigned up   = bit1(&nucw[(yi+3)*3], xi + 32);
    unsigned dn   = bit1(&nucw[(yi+5)*3], xi + 32);
    unsigned lf   = bit1(&nucw[(yi+4)*3], xi + 31);
    unsigned rt   = bit1(&nucw[(yi+4)*3], xi + 33);
    float lap = fabsf((float)(up + dn + lf + rt) - 4.0f*(float)cbit);
    unsigned bc = bit1(&bndw[(yi+4)*3], xi + 32);
    int bs = 0;
    #pragma unroll
    for (int k = 0; k < 5; k++)
        bs += __popc(winN(&bndw[(yi+2+k)*3], xi + 30, 5));
    float rough = lap*(float)bc / ((float)bs + 1e-6f);

    // write raw z maps + nuc
    size_t pix = (size_t)gy*WW + gx;
    float* z = out + (size_t)NPIX + (size_t)b*4*HW + pix;
    z[0]     = rough;
    z[HW]    = circ;
    z[2*HW]  = ncv;
    z[3*HW]  = ent;
    out[5*(size_t)NPIX + (size_t)b*HW + pix] = (float)cbit;

    // energy
    float z0s = log1pf(fmaxf(rough, 0.0f));
    float z1s = fminf(fmaxf(circ, 0.0f), 1.0f);
    float z2s = log1pf(fmaxf(ncv, 0.0f));
    float z3s = fminf(fmaxf(ent, 0.0f), 3.4657359f);
    float E = g_par[8 ]*(g_par[0]*z0s + g_par[4])
            + g_par[9 ]*(g_par[1]*z1s + g_par[5])
            + g_par[10]*(g_par[2]*z2s + g_par[6])
            + g_par[11]*(g_par[3]*z3s + g_par[7]);
    out[6*(size_t)NPIX + (size_t)b*HW + pix] = E;

    // per-tile softmax partials (reuse ssn as reduction buffer; last read in stage2)
    float invtau = 1.0f / g_par[12];
    float zz = -E*invtau;
    float* red = ssn;
    red[tid] = zz;
    __syncthreads();
    for (int s = 512; s > 0; s >>= 1){
        if (tid < s) red[tid] = fmaxf(red[tid], red[tid + s]);
        __syncthreads();
    }
    float m = red[0];
    __syncthreads();
    red[tid] = expf(zz - m);
    __syncthreads();
    for (int s = 512; s > 0; s >>= 1){
        if (tid < s) red[tid] += red[tid + s];
        __syncthreads();
    }
    if (tid == 0){
        int tile = blockIdx.y*16 + blockIdx.x;
        g_part[(b*256 + tile)*2    ] = m;
        g_part[(b*256 + tile)*2 + 1] = red[0];
    }
}

// ---------------- combine softmax partials ----------------
__global__ void k_combine(){
    __shared__ float sm[256], ss[256];
    int b = blockIdx.x, t = threadIdx.x;
    float m = g_part[(b*256 + t)*2];
    float s = g_part[(b*256 + t)*2 + 1];
    sm[t] = m;
    __syncthreads();
    for (int st = 128; st > 0; st >>= 1){
        if (t < st) sm[t] = fmaxf(sm[t], sm[t + st]);
        __syncthreads();
    }
    float M = sm[0];
    __syncthreads();
    ss[t] = s*expf(m - M);
    __syncthreads();
    for (int st = 128; st > 0; st >>= 1){
        if (t < st) ss[t] += ss[t + st];
        __syncthreads();
    }
    if (t == 0){ g_red[b*2] = M; g_red[b*2 + 1] = ss[0]; }
}

// ---------------- final A ----------------
__global__ void k_A(float* __restrict__ out){
    int b = blockIdx.y;
    int p = blockIdx.x*blockDim.x + threadIdx.x;
    float invtau = 1.0f / g_par[12];
    float M = g_red[b*2];
    float S = g_red[b*2 + 1];
    float E = out[6*(size_t)NPIX + (size_t)b*HW + p];
    out[(size_t)b*HW + p] = expf(-E*invtau - M) / S;
}

// ---------------- launch ----------------
extern "C" void kernel_launch(void* const* d_in, const int* in_sizes, int n_in,
                              void* d_out, int out_size){
    const float* img    = (const float*)d_in[0];
    const float* cal_a  = (const float*)d_in[1];
    const float* cal_b  = (const float*)d_in[2];
    const float* alpha  = (const float*)d_in[3];
    const float* tau_p  = (const float*)d_in[4];
    float* out = (float*)d_out;
    (void)in_sizes; (void)n_in; (void)out_size;

    dim3 blk1(256, 1, 1);
    dim3 grd1(HW/256, BB, 1);

    k_zero_hist<<<2, 256>>>();
    k_gray_hist<<<grd1, blk1>>>(img);
    k_otsu_params<<<BB, 32>>>(cal_a, cal_b, alpha, tau_p);
    k_morph<<<BB, 1024>>>();
    k_fused<<<dim3(16, 16, BB), dim3(32, 32, 1)>>>(out);
    k_combine<<<BB, 256>>>();
    k_A<<<grd1, blk1>>>(out);
}